// round 2
// baseline (speedup 1.0000x reference)
#include <cuda_runtime.h>
#include <cuda_bf16.h>

// Node constants packed per node as 4 float4 (64B):
//   q0 = (r00, r01, r02, u0)
//   q1 = (r10, r11, r12, u1)
//   q2 = (r20, r21, r22, u2)
//   q3 = (cx,  cy,  cz,  0 )
// where u = t + c - R*c, so contribution = w * (R*p + u).
#define MAXN 4096
__device__ float4 g_node[MAXN * 4];

// ---------------------------------------------------------------------------
// Kernel 1: Rodrigues + per-node constant precompute (tiny: N=512)
// ---------------------------------------------------------------------------
__global__ void prep_kernel(const float* __restrict__ cp,
                            const float* __restrict__ rv,
                            const float* __restrict__ t,
                            int N) {
    int n = blockIdx.x * blockDim.x + threadIdx.x;
    if (n >= N) return;

    float x = rv[3 * n + 0], y = rv[3 * n + 1], z = rv[3 * n + 2];
    float th2 = x * x + y * y + z * z + 1e-12f;
    float th = sqrtf(th2);
    float s, co;
    sincosf(th, &s, &co);
    float a = s / th;            // sin(th)/th
    float b = (1.0f - co) / th2; // (1-cos(th))/th^2

    // R = I + a*skew(w) + b*skew(w)^2
    float xx = x * x, yy = y * y, zz = z * z;
    float xy = x * y, xz = x * z, yz = y * z;
    float r00 = 1.0f - b * (yy + zz);
    float r01 = -a * z + b * xy;
    float r02 =  a * y + b * xz;
    float r10 =  a * z + b * xy;
    float r11 = 1.0f - b * (xx + zz);
    float r12 = -a * x + b * yz;
    float r20 = -a * y + b * xz;
    float r21 =  a * x + b * yz;
    float r22 = 1.0f - b * (xx + yy);

    float cx = cp[3 * n + 0], cy = cp[3 * n + 1], cz = cp[3 * n + 2];
    float tx = t[3 * n + 0],  ty = t[3 * n + 1],  tz = t[3 * n + 2];

    float u0 = tx + cx - (r00 * cx + r01 * cy + r02 * cz);
    float u1 = ty + cy - (r10 * cx + r11 * cy + r12 * cz);
    float u2 = tz + cz - (r20 * cx + r21 * cy + r22 * cz);

    g_node[n * 4 + 0] = make_float4(r00, r01, r02, u0);
    g_node[n * 4 + 1] = make_float4(r10, r11, r12, u1);
    g_node[n * 4 + 2] = make_float4(r20, r21, r22, u2);
    g_node[n * 4 + 3] = make_float4(cx, cy, cz, 0.0f);
}

// ---------------------------------------------------------------------------
// Kernel 2: main P x N warp field. One thread per point, node constants
// staged in shared memory (uniform-address LDS.128 broadcast).
// ---------------------------------------------------------------------------
__global__ void __launch_bounds__(128)
warp_kernel(const float* __restrict__ pts,
            float* __restrict__ out,
            int N, int P) {
    extern __shared__ float4 sm[];
    for (int i = threadIdx.x; i < N * 4; i += blockDim.x)
        sm[i] = g_node[i];
    __syncthreads();

    int pi = blockIdx.x * blockDim.x + threadIdx.x;
    if (pi >= P) return;

    float px = pts[3 * pi + 0];
    float py = pts[3 * pi + 1];
    float pz = pts[3 * pi + 2];

    float ax = 0.0f, ay = 0.0f, az = 0.0f, S = 0.0f;

    const float kExpScale = -0.02f; // -1/(2*sigma^2) = -1/50

#pragma unroll 4
    for (int n = 0; n < N; ++n) {
        float4 q0 = sm[n * 4 + 0];
        float4 q1 = sm[n * 4 + 1];
        float4 q2 = sm[n * 4 + 2];
        float4 q3 = sm[n * 4 + 3];

        float dx = px - q3.x;
        float dy = py - q3.y;
        float dz = pz - q3.z;
        float d2 = fmaf(dx, dx, fmaf(dy, dy, dz * dz));
        float w = __expf(d2 * kExpScale);

        float y0 = fmaf(q0.x, px, fmaf(q0.y, py, fmaf(q0.z, pz, q0.w)));
        float y1 = fmaf(q1.x, px, fmaf(q1.y, py, fmaf(q1.z, pz, q1.w)));
        float y2 = fmaf(q2.x, px, fmaf(q2.y, py, fmaf(q2.z, pz, q2.w)));

        ax = fmaf(w, y0, ax);
        ay = fmaf(w, y1, ay);
        az = fmaf(w, y2, az);
        S += w;
    }

    float inv = 1.0f / (S + 1e-5f);
    out[3 * pi + 0] = ax * inv;
    out[3 * pi + 1] = ay * inv;
    out[3 * pi + 2] = az * inv;
}

// ---------------------------------------------------------------------------
// Kernel 3: edge regularizer, single block, deterministic tree reduction.
// resid = R_i (c_j - c_i) + c_i + t_i - (c_j + t_j); reg = sum |resid|^2
// NOTE: edges arrive as int32 (JAX x64 disabled downcasts int64 -> int32).
// ---------------------------------------------------------------------------
__global__ void edge_kernel(const float* __restrict__ cp,
                            const float* __restrict__ t,
                            const int* __restrict__ edges,
                            float* __restrict__ out,
                            int E, int P, int N) {
    __shared__ float red[1024];
    float acc = 0.0f;

    for (int m = threadIdx.x; m < E; m += blockDim.x) {
        int i = edges[2 * m + 0];
        int j = edges[2 * m + 1];
        // defensive clamp (no-op for valid data, prevents OOB fault)
        i = min(max(i, 0), N - 1);
        j = min(max(j, 0), N - 1);

        float4 q0 = g_node[i * 4 + 0];
        float4 q1 = g_node[i * 4 + 1];
        float4 q2 = g_node[i * 4 + 2];

        float cix = cp[3 * i + 0], ciy = cp[3 * i + 1], ciz = cp[3 * i + 2];
        float cjx = cp[3 * j + 0], cjy = cp[3 * j + 1], cjz = cp[3 * j + 2];
        float tix = t[3 * i + 0],  tiy = t[3 * i + 1],  tiz = t[3 * i + 2];
        float tjx = t[3 * j + 0],  tjy = t[3 * j + 1],  tjz = t[3 * j + 2];

        float dx = cjx - cix, dy = cjy - ciy, dz = cjz - ciz;

        float r0 = fmaf(q0.x, dx, fmaf(q0.y, dy, q0.z * dz)) + cix + tix - cjx - tjx;
        float r1 = fmaf(q1.x, dx, fmaf(q1.y, dy, q1.z * dz)) + ciy + tiy - cjy - tjy;
        float r2 = fmaf(q2.x, dx, fmaf(q2.y, dy, q2.z * dz)) + ciz + tiz - cjz - tjz;

        acc += r0 * r0 + r1 * r1 + r2 * r2;
    }

    red[threadIdx.x] = acc;
    __syncthreads();
    for (int s = blockDim.x / 2; s > 0; s >>= 1) {
        if (threadIdx.x < (unsigned)s) red[threadIdx.x] += red[threadIdx.x + s];
        __syncthreads();
    }
    if (threadIdx.x == 0) out[3 * P] = red[0];
}

// ---------------------------------------------------------------------------
// Launch
// ---------------------------------------------------------------------------
extern "C" void kernel_launch(void* const* d_in, const int* in_sizes, int n_in,
                              void* d_out, int out_size) {
    const float* points  = (const float*)d_in[0];
    const float* cp      = (const float*)d_in[1];
    const float* rot_vec = (const float*)d_in[2];
    const float* t       = (const float*)d_in[3];
    const int*   edges   = (const int*)d_in[4];

    float* out = (float*)d_out;

    int P = in_sizes[0] / 3;
    int N = in_sizes[1] / 3;
    int E = in_sizes[4] / 2;
    if (N > MAXN) N = MAXN; // defensive

    // 1. Per-node constants
    prep_kernel<<<(N + 255) / 256, 256>>>(cp, rot_vec, t, N);

    // 2. Main warp field
    int block = 128;
    int grid = (P + block - 1) / block;
    size_t smem = (size_t)N * 4 * sizeof(float4);
    warp_kernel<<<grid, block, smem>>>(points, out, N, P);

    // 3. Edge regularizer (writes out[3*P], deterministic)
    edge_kernel<<<1, 1024>>>(cp, t, edges, out, E, P, N);
}